// round 4
// baseline (speedup 1.0000x reference)
#include <cuda_runtime.h>
#include <cuda_fp16.h>
#include <cstdint>

#define THREADS     256
#define B_ROWS      256
#define D_K         2048
#define N_FEAT      65536
#define N_TILE      64
#define KC          64
#define NSTAGE      (D_K / KC)            // 32
#define A_ST        (B_ROWS * KC * 2)     // 32768 fp16 A
#define B_ST        (N_TILE * KC * 4)     // 16384 fp32 B
#define STAGE_BYTES (A_ST + B_ST)         // 49152
#define SMEM_DYN    (1024 + 2 * STAGE_BYTES)

// 1MB fp16 copy of `inputs` (pre-converted once per launch, L2-resident)
__device__ __half g_a16[B_ROWS * D_K];

static __device__ __forceinline__ uint32_t smem_u32(const void* p) {
    uint32_t a;
    asm("{ .reg .u64 t; cvta.to.shared.u64 t, %1; cvt.u32.u64 %0, t; }"
        : "=r"(a) : "l"(p));
    return a;
}

#define CP_ASYNC16(dst, src) \
    asm volatile("cp.async.cg.shared.global [%0], [%1], 16;" \
                 :: "r"(dst), "l"(src) : "memory")
#define CP_COMMIT() asm volatile("cp.async.commit_group;" ::: "memory")
#define CP_WAIT1()  asm volatile("cp.async.wait_group 1;"  ::: "memory")
#define CP_WAIT0()  asm volatile("cp.async.wait_group 0;"  ::: "memory")

#define LDSM_X4(r, addr) \
    asm volatile("ldmatrix.sync.aligned.m8n8.x4.shared.b16 {%0,%1,%2,%3}, [%4];" \
        : "=r"((r)[0]), "=r"((r)[1]), "=r"((r)[2]), "=r"((r)[3]) : "r"(addr))

#define LDS64F(x, y, addr) \
    asm volatile("ld.shared.v2.f32 {%0,%1}, [%2];" \
        : "=f"(x), "=f"(y) : "r"(addr))

#define MMA16816(c, a, b0, b1) \
    asm volatile("mma.sync.aligned.m16n8k16.row.col.f32.f16.f16.f32 " \
        "{%0,%1,%2,%3}, {%4,%5,%6,%7}, {%8,%9}, {%0,%1,%2,%3};" \
        : "+f"((c)[0]), "+f"((c)[1]), "+f"((c)[2]), "+f"((c)[3]) \
        : "r"((a)[0]), "r"((a)[1]), "r"((a)[2]), "r"((a)[3]), "r"(b0), "r"(b1))

// ---------------- pre-kernel: inputs fp32 -> fp16 scratch ----------------
__global__ void cvt_a_kernel(const float* __restrict__ inputs) {
    int i = blockIdx.x * blockDim.x + threadIdx.x;
    if (i < (B_ROWS * D_K) / 2) {
        float2 v = reinterpret_cast<const float2*>(inputs)[i];
        reinterpret_cast<__half2*>(g_a16)[i] = __floats2half2_rn(v.x, v.y);
    }
}

// ---------------- main GEMM kernel ----------------
__global__ __launch_bounds__(THREADS, 2)
void gemm_hmma_kernel(const float* __restrict__ feats, float* __restrict__ out) {
    extern __shared__ char dsm[];
    const uint32_t raw = smem_u32(dsm);
    const uint32_t SB = (raw + 1023u) & ~1023u;

    const int tid = threadIdx.x;
    const int wid = tid >> 5;
    const int lid = tid & 31;
    const int wm  = wid & 3;    // 4 M-warps x 64 rows
    const int wn  = wid >> 2;   // 2 N-warps x 32 cols
    const int n0  = blockIdx.x * N_TILE;

    // ---- cp.async staging (per-thread constants) ----
    // A: 256 rows x 128B fp16/stage; 8 chunks of 16B per thread
    const char* aSrc = (const char*)(g_a16 + (size_t)(tid >> 3) * D_K + (tid & 7) * 8);
    const uint32_t aOff = ((uint32_t)(tid >> 3) << 7) |
                          ((uint32_t)((tid & 7) ^ ((tid >> 3) & 7)) << 4);
    // B: 64 rows x 256B fp32/stage; 4 chunks of 16B per thread
    const char* bSrc = (const char*)(feats + (size_t)(n0 + (tid >> 4)) * D_K + (tid & 15) * 4);
    const uint32_t cB = (uint32_t)(tid & 15);
    const uint32_t bOff = ((uint32_t)(tid >> 4) << 8) |
                          (((cB & 8u) | ((cB & 7u) ^ ((uint32_t)(tid >> 4) & 7u))) << 4);

    // ---- fragment addressing (per-lane constants) ----
    const uint32_t a_lane = (uint32_t)(wm * 64 + (lid & 15)) << 7;  // row*128
    const uint32_t a_sw   = (uint32_t)(lid & 7);
    const uint32_t a_kc   = (uint32_t)(lid >> 4);
    const uint32_t b_lane = ((uint32_t)(wn * 32 + (lid >> 2)) << 8) | ((uint32_t)(lid & 1) << 3);
    const uint32_t b_sw   = (uint32_t)(lid >> 2) & 7u;
    const uint32_t b_cb   = (uint32_t)((lid >> 1) & 1);

    float acc[4][4][4];
    #pragma unroll
    for (int mf = 0; mf < 4; ++mf)
        #pragma unroll
        for (int nf = 0; nf < 4; ++nf)
            #pragma unroll
            for (int k = 0; k < 4; ++k)
                acc[mf][nf][k] = 0.0f;

    // ---- issue helper (inlined manually) ----
    auto issue = [&](int s) {
        const uint32_t Ab = SB + (uint32_t)(s & 1) * STAGE_BYTES;
        const uint32_t Bb = Ab + A_ST;
        const char* as = aSrc + (size_t)s * (KC * 2);
        const char* bs = bSrc + (size_t)s * (KC * 4);
        #pragma unroll
        for (int i = 0; i < 8; ++i)
            CP_ASYNC16(Ab + aOff + i * 4096, as + (size_t)i * 32 * D_K * 2);
        #pragma unroll
        for (int i = 0; i < 4; ++i)
            CP_ASYNC16(Bb + bOff + i * 4096, bs + (size_t)i * 16 * D_K * 4);
    };

    issue(0);
    CP_COMMIT();

    for (int s = 0; s < NSTAGE; ++s) {
        if (s + 1 < NSTAGE) {
            issue(s + 1);
            CP_COMMIT();
            CP_WAIT1();
        } else {
            CP_WAIT0();
        }
        __syncthreads();

        const uint32_t Ab = SB + (uint32_t)(s & 1) * STAGE_BYTES;
        const uint32_t Bb = Ab + A_ST;

        #pragma unroll
        for (int ks = 0; ks < 4; ++ks) {
            // A fragments: 4x ldmatrix.x4
            uint32_t ar[4][4];
            const uint32_t a_ch = ((a_kc + 2u * ks) ^ a_sw) << 4;
            #pragma unroll
            for (int mf = 0; mf < 4; ++mf)
                LDSM_X4(ar[mf], Ab + a_lane + (uint32_t)(mf * 2048) + a_ch);

            // B fragments: fp32 LDS + cvt to fp16 (canonical m16n8k16 layout)
            uint32_t bfr[4][2];
            const uint32_t c0 = 4u * ks + b_cb;
            const uint32_t c1 = c0 + 2u;
            const uint32_t sw0 = ((c0 & 8u) | ((c0 & 7u) ^ b_sw)) << 4;
            const uint32_t sw1 = ((c1 & 8u) | ((c1 & 7u) ^ b_sw)) << 4;
            #pragma unroll
            for (int nf = 0; nf < 4; ++nf) {
                float x0, y0, x1, y1;
                LDS64F(x0, y0, Bb + b_lane + (uint32_t)(nf * 2048) + sw0);
                LDS64F(x1, y1, Bb + b_lane + (uint32_t)(nf * 2048) + sw1);
                __half2 h0 = __floats2half2_rn(x0, y0);
                __half2 h1 = __floats2half2_rn(x1, y1);
                bfr[nf][0] = *reinterpret_cast<uint32_t*>(&h0);
                bfr[nf][1] = *reinterpret_cast<uint32_t*>(&h1);
            }

            #pragma unroll
            for (int mf = 0; mf < 4; ++mf)
                #pragma unroll
                for (int nf = 0; nf < 4; ++nf)
                    MMA16816(acc[mf][nf], ar[mf], bfr[nf][0], bfr[nf][1]);
        }
        __syncthreads();
    }

    // ---- epilogue: direct STG.64, 32B-sector aligned ----
    const int mrow = wm * 64 + (lid >> 2);
    const int ncol = n0 + wn * 32 + 2 * (lid & 3);
    #pragma unroll
    for (int mf = 0; mf < 4; ++mf) {
        float* r0 = out + (size_t)(mrow + mf * 16) * N_FEAT;
        float* r1 = r0 + (size_t)8 * N_FEAT;
        #pragma unroll
        for (int nf = 0; nf < 4; ++nf) {
            const int c = ncol + nf * 8;
            *reinterpret_cast<float2*>(r0 + c) =
                make_float2(acc[mf][nf][0], acc[mf][nf][1]);
            *reinterpret_cast<float2*>(r1 + c) =
                make_float2(acc[mf][nf][2], acc[mf][nf][3]);
        }
    }
}

// ---------------- launch ----------------
extern "C" void kernel_launch(void* const* d_in, const int* in_sizes, int n_in,
                              void* d_out, int out_size) {
    const float* inputs = (const float*)d_in[0];   // [256, 2048] fp32
    const float* feats  = (const float*)d_in[3];   // [65536, 2048] fp32
    float* out = (float*)d_out;                    // [256, 65536] fp32

    cudaFuncSetAttribute(gemm_hmma_kernel,
                         cudaFuncAttributeMaxDynamicSharedMemorySize, SMEM_DYN);

    cvt_a_kernel<<<(B_ROWS * D_K / 2 + 255) / 256, 256>>>(inputs);
    gemm_hmma_kernel<<<N_FEAT / N_TILE, THREADS, SMEM_DYN>>>(feats, out);
}

// round 6
// speedup vs baseline: 1.1305x; 1.1305x over previous
#include <cuda_runtime.h>
#include <cuda_fp16.h>
#include <cstdint>

#define THREADS     256
#define B_ROWS      256
#define D_K         2048
#define N_FEAT      65536
#define N_TILE      64
#define KC          64
#define NSTAGE      (D_K / KC)            // 32
#define A_ST        (B_ROWS * KC * 2)     // 32768 fp16 A
#define B_ST        (N_TILE * KC * 2)     // 8192  fp16 B
#define STAGE_BYTES (A_ST + B_ST)         // 40960
#define SMEM_DYN    (1024 + 2 * STAGE_BYTES)

// 1MB fp16 copy of `inputs` (pre-converted once per launch, L2-resident)
__device__ __half g_a16[B_ROWS * D_K];

static __device__ __forceinline__ uint32_t smem_u32(const void* p) {
    uint32_t a;
    asm("{ .reg .u64 t; cvta.to.shared.u64 t, %1; cvt.u32.u64 %0, t; }"
        : "=r"(a) : "l"(p));
    return a;
}

#define CP_ASYNC16(dst, src) \
    asm volatile("cp.async.cg.shared.global [%0], [%1], 16;" \
                 :: "r"(dst), "l"(src) : "memory")
#define CP_COMMIT() asm volatile("cp.async.commit_group;" ::: "memory")
#define CP_WAIT0()  asm volatile("cp.async.wait_group 0;"  ::: "memory")

#define LDSM_X4(r, addr) \
    asm volatile("ldmatrix.sync.aligned.m8n8.x4.shared.b16 {%0,%1,%2,%3}, [%4];" \
        : "=r"((r)[0]), "=r"((r)[1]), "=r"((r)[2]), "=r"((r)[3]) : "r"(addr))

#define MMA16816(c, a, b0, b1) \
    asm volatile("mma.sync.aligned.m16n8k16.row.col.f32.f16.f16.f32 " \
        "{%0,%1,%2,%3}, {%4,%5,%6,%7}, {%8,%9}, {%0,%1,%2,%3};" \
        : "+f"((c)[0]), "+f"((c)[1]), "+f"((c)[2]), "+f"((c)[3]) \
        : "r"((a)[0]), "r"((a)[1]), "r"((a)[2]), "r"((a)[3]), "r"(b0), "r"(b1))

#define STS64(addr, v0, v1) \
    asm volatile("st.shared.v2.b32 [%0], {%1,%2};" \
                 :: "r"(addr), "r"(v0), "r"(v1) : "memory")

// ---------------- pre-kernel: inputs fp32 -> fp16 scratch ----------------
__global__ void cvt_a_kernel(const float* __restrict__ inputs) {
    int i = blockIdx.x * blockDim.x + threadIdx.x;
    if (i < (B_ROWS * D_K) / 2) {
        float2 v = reinterpret_cast<const float2*>(inputs)[i];
        reinterpret_cast<__half2*>(g_a16)[i] = __floats2half2_rn(v.x, v.y);
    }
}

// ---------------- main GEMM kernel ----------------
__global__ __launch_bounds__(THREADS, 2)
void gemm_hmma_kernel(const float* __restrict__ feats, float* __restrict__ out) {
    extern __shared__ char dsm[];
    const uint32_t raw = smem_u32(dsm);
    const uint32_t SB = (raw + 1023u) & ~1023u;

    const int tid = threadIdx.x;
    const int wid = tid >> 5;
    const int lid = tid & 31;
    const int wm  = wid & 3;    // 4 M-warps x 64 rows
    const int wn  = wid >> 2;   // 2 N-warps x 32 cols
    const int n0  = blockIdx.x * N_TILE;

    // ---- A cp.async staging: 256 rows x 128B/stage; 8x16B per thread ----
    const char* aSrc = (const char*)(g_a16 + (size_t)(tid >> 3) * D_K + (tid & 7) * 8);
    const uint32_t aOff = ((uint32_t)(tid >> 3) << 7) |
                          ((uint32_t)((tid & 7) ^ ((tid >> 3) & 7)) << 4);

    // ---- B LDG staging: 64 rows x 64 fp32/stage; 4x float4 per thread ----
    const int brow = tid >> 2;
    const int bj   = tid & 3;
    const float* bSrc = feats + (size_t)(n0 + brow) * D_K + bj * 4;
    uint32_t bsts_off[4];
    #pragma unroll
    for (int i = 0; i < 4; ++i) {
        uint32_t ob = ((uint32_t)brow << 7) | ((uint32_t)(bj + 4 * i) << 3);
        bsts_off[i] = ob ^ ((ob >> 3) & 0x70);
    }

    // ---- ldmatrix fragment addressing (swizzle-correct per k-step) ----
    const uint32_t a_lane = (uint32_t)(wm * 64 + (lid & 15)) << 7;
    const uint32_t a_sw   = (uint32_t)(lid & 7);
    const uint32_t a_kc   = (uint32_t)(lid >> 4);
    const uint32_t b_row  = (uint32_t)(wn * 32 + ((lid >> 4) << 3) + (lid & 7));
    const uint32_t b_lane = b_row << 7;
    const uint32_t b_sw   = b_row & 7;
    const uint32_t b_kc   = (uint32_t)((lid >> 3) & 1);

    float acc[4][4][4];
    #pragma unroll
    for (int mf = 0; mf < 4; ++mf)
        #pragma unroll
        for (int nf = 0; nf < 4; ++nf)
            #pragma unroll
            for (int k = 0; k < 4; ++k)
                acc[mf][nf][k] = 0.0f;

    float fst[16];   // staged raw fp32 B for current stage

    // ---- prologue: B(0) LDG + A(0) cp.async ----
    #pragma unroll
    for (int i = 0; i < 4; ++i) {
        const float4 v = *reinterpret_cast<const float4*>(bSrc + i * 16);
        fst[i*4+0] = v.x; fst[i*4+1] = v.y; fst[i*4+2] = v.z; fst[i*4+3] = v.w;
    }
    #pragma unroll
    for (int i = 0; i < 8; ++i)
        CP_ASYNC16(SB + aOff + i * 4096, aSrc + (size_t)i * 32 * D_K * 2);
    CP_COMMIT();

    for (int s = 0; s < NSTAGE; ++s) {
        const int buf = s & 1;
        const uint32_t Ab = SB + buf * STAGE_BYTES;
        const uint32_t Bb = Ab + A_ST;

        // STS B(s): convert staged fp32 -> fp16
        #pragma unroll
        for (int i = 0; i < 4; ++i) {
            __half2 h0 = __floats2half2_rn(fst[i*4+0], fst[i*4+1]);
            __half2 h1 = __floats2half2_rn(fst[i*4+2], fst[i*4+3]);
            STS64(Bb + bsts_off[i],
                  *reinterpret_cast<uint32_t*>(&h0),
                  *reinterpret_cast<uint32_t*>(&h1));
        }
        CP_WAIT0();          // A(s) landed
        __syncthreads();

        // issue stage s+1 loads (covered by compute below)
        if (s + 1 < NSTAGE) {
            const int kc1 = (s + 1) * KC;   // in FLOAT elements
            #pragma unroll
            for (int i = 0; i < 4; ++i) {
                const float4 v = *reinterpret_cast<const float4*>(bSrc + kc1 + i * 16);
                fst[i*4+0] = v.x; fst[i*4+1] = v.y; fst[i*4+2] = v.z; fst[i*4+3] = v.w;
            }
            const uint32_t An = SB + (buf ^ 1) * STAGE_BYTES;
            const char* as = aSrc + (size_t)(s + 1) * (KC * 2);
            #pragma unroll
            for (int i = 0; i < 8; ++i)
                CP_ASYNC16(An + aOff + i * 4096, as + (size_t)i * 32 * D_K * 2);
            CP_COMMIT();
        }

        // ---- compute stage s: 4 k-steps of 16 ----
        #pragma unroll
        for (int ks = 0; ks < 4; ++ks) {
            uint32_t ar[4][4], br[4];
            const uint32_t a_ch = ((a_kc + 2u * ks) ^ a_sw) << 4;
            #pragma unroll
            for (int mf = 0; mf < 4; ++mf)
                LDSM_X4(ar[mf], Ab + a_lane + (uint32_t)(mf * 2048) + a_ch);
            const uint32_t b_ch = ((b_kc + 2u * ks) ^ b_sw) << 4;
            LDSM_X4(br, Bb + b_lane + b_ch);   // this warp's cols 0-15 (nf 0,1)
            #pragma unroll
            for (int mf = 0; mf < 4; ++mf) {
                MMA16816(acc[mf][0], ar[mf], br[0], br[1]);
                MMA16816(acc[mf][1], ar[mf], br[2], br[3]);
            }
            uint32_t br2[4];
            const uint32_t b_lane2 = (b_row + 16u) << 7;   // cols 16-31 (nf 2,3)
            LDSM_X4(br2, Bb + b_lane2 + b_ch);             // same swizzle: (row+16)&7 == row&7
            #pragma unroll
            for (int mf = 0; mf < 4; ++mf) {
                MMA16816(acc[mf][2], ar[mf], br2[0], br2[1]);
                MMA16816(acc[mf][3], ar[mf], br2[2], br2[3]);
            }
        }
        __syncthreads();
    }

    // ---- epilogue: direct STG.64, 32B-sector aligned ----
    const int mrow = wm * 64 + (lid >> 2);
    const int ncol = n0 + wn * 32 + 2 * (lid & 3);
    #pragma unroll
    for (int mf = 0; mf < 4; ++mf) {
        float* r0 = out + (size_t)(mrow + mf * 16) * N_FEAT;
        float* r1 = r0 + (size_t)8 * N_FEAT;
        #pragma unroll
        for (int nf = 0; nf < 4; ++nf) {
            const int c = ncol + nf * 8;
            *reinterpret_cast<float2*>(r0 + c) =
                make_float2(acc[mf][nf][0], acc[mf][nf][1]);
            *reinterpret_cast<float2*>(r1 + c) =
                make_float2(acc[mf][nf][2], acc[mf][nf][3]);
        }
    }
}

// ---------------- launch ----------------
extern "C" void kernel_launch(void* const* d_in, const int* in_sizes, int n_in,
                              void* d_out, int out_size) {
    const float* inputs = (const float*)d_in[0];   // [256, 2048] fp32
    const float* feats  = (const float*)d_in[3];   // [65536, 2048] fp32
    float* out = (float*)d_out;                    // [256, 65536] fp32

    cudaFuncSetAttribute(gemm_hmma_kernel,
                         cudaFuncAttributeMaxDynamicSharedMemorySize, SMEM_DYN);

    cvt_a_kernel<<<(B_ROWS * D_K / 2 + 255) / 256, 256>>>(inputs);
    gemm_hmma_kernel<<<N_FEAT / N_TILE, THREADS, SMEM_DYN>>>(feats, out);
}